// round 1
// baseline (speedup 1.0000x reference)
#include <cuda_runtime.h>

// ---------------------------------------------------------------------------
// QWTForward collapses to: D = bicubic_down2(image); out[q][b] = D * (S_a*S_b)
// where S_* are sums of the 4 filter tap arrays (the reference's filt(x,h)
// is exactly x * sum(h)).
//
// Output layout (4 tensors concatenated in d_out, each (N,12,256,256)):
//   tensor q, block b (channel group b*3+c):
//     first-factor sum index  fi = (b&1)*2 + (q>=2)   over [gl,gh,fl,fh]
//     second-factor sum index si = (b>=2)*2 + (q&1)
// ---------------------------------------------------------------------------

__device__ float g_sc[16];

__global__ void qwt_scalars_kernel(const float* __restrict__ gl,
                                   const float* __restrict__ gh,
                                   const float* __restrict__ fl,
                                   const float* __restrict__ fh,
                                   int L) {
    // single thread; L ~ 30 taps
    float s[4] = {0.f, 0.f, 0.f, 0.f};
    for (int i = 0; i < L; i++) {
        s[0] += gl[i];
        s[1] += gh[i];
        s[2] += fl[i];
        s[3] += fh[i];
    }
#pragma unroll
    for (int q = 0; q < 4; q++) {
#pragma unroll
        for (int b = 0; b < 4; b++) {
            int fi = ((b & 1) << 1) | (q >> 1);
            int si = ((b >> 1) << 1) | (q & 1);
            g_sc[q * 4 + b] = s[fi] * s[si];
        }
    }
}

// One thread per output pixel of D (N*3 channels x 256 x 256).
// Bicubic scale-0.5 stencil, fixed fractional offset 0.5:
//   taps at input coords 2i-1 .. 2i+2, weights (-0.09375, 0.59375, 0.59375, -0.09375),
//   edge-clamped. Separable W then H (weights symmetric -> fold pairs).
__global__ __launch_bounds__(256) void qwt_main_kernel(
    const float* __restrict__ img, float* __restrict__ out, int NC) {
    unsigned idx = blockIdx.x * 256u + threadIdx.x;
    unsigned x  = idx & 255u;
    unsigned y  = (idx >> 8) & 255u;
    unsigned nc = idx >> 16;

    const float* src = img + (size_t)nc * (512u * 512u);

    const int xb = 2 * (int)x - 1;
    const int yb = 2 * (int)y - 1;
    const int x0 = max(xb, 0);
    const int x1 = xb + 1;
    const int x2 = xb + 2;
    const int x3 = min(xb + 3, 511);
    const int y0 = max(yb, 0);
    const int y3 = min(yb + 3, 511);

    const float w0 = -0.09375f;
    const float w1 =  0.59375f;

    const float* r0 = src + (size_t)y0 * 512;
    const float* r1 = src + (size_t)(yb + 1) * 512;
    const float* r2 = src + (size_t)(yb + 2) * 512;
    const float* r3 = src + (size_t)y3 * 512;

    float h0 = w0 * (__ldg(r0 + x0) + __ldg(r0 + x3)) + w1 * (__ldg(r0 + x1) + __ldg(r0 + x2));
    float h1 = w0 * (__ldg(r1 + x0) + __ldg(r1 + x3)) + w1 * (__ldg(r1 + x1) + __ldg(r1 + x2));
    float h2 = w0 * (__ldg(r2 + x0) + __ldg(r2 + x3)) + w1 * (__ldg(r2 + x1) + __ldg(r2 + x2));
    float h3 = w0 * (__ldg(r3 + x0) + __ldg(r3 + x3)) + w1 * (__ldg(r3 + x1) + __ldg(r3 + x2));

    const float dval = w0 * (h0 + h3) + w1 * (h1 + h2);

    const unsigned n = nc / 3u;
    const unsigned c = nc - 3u * n;
    const size_t plane = 256u * 256u;
    const size_t base  = ((size_t)(n * 12u + c)) * plane + (size_t)y * 256u + x;
    const size_t QS    = (size_t)(NC / 3) * 12u * plane;  // elements per output tensor

    const float4* scv = (const float4*)g_sc;
#pragma unroll
    for (int q = 0; q < 4; q++) {
        const float4 sv = scv[q];
        float* o = out + base + (size_t)q * QS;
        o[0]         = dval * sv.x;
        o[3 * plane] = dval * sv.y;
        o[6 * plane] = dval * sv.z;
        o[9 * plane] = dval * sv.w;
    }
}

extern "C" void kernel_launch(void* const* d_in, const int* in_sizes, int n_in,
                              void* d_out, int out_size) {
    const float* img = (const float*)d_in[0];
    const float* gl  = (const float*)d_in[1];
    const float* gh  = (const float*)d_in[2];
    const float* fl  = (const float*)d_in[3];
    const float* fh  = (const float*)d_in[4];

    const int L  = in_sizes[1];                 // filter length (30)
    const int NC = in_sizes[0] / (512 * 512);   // N*3 = 48 channels

    qwt_scalars_kernel<<<1, 1>>>(gl, gh, fl, fh, L);

    const int total_threads = NC * 256 * 256;   // one per D pixel
    qwt_main_kernel<<<total_threads / 256, 256>>>(img, (float*)d_out, NC);
}